// round 15
// baseline (speedup 1.0000x reference)
#include <cuda_runtime.h>
#include <cuda_fp16.h>
#include <cstdint>
#include <math.h>

#define NB 4096
#define NI 256
#define NO 256
#define KSP 3072   /* real K (6 pairs * 512) */
#define KST 1536   /* stored K */
#define NCH 24     /* chunks of 128 real / 64 stored k */

__device__ __half    g_A[(size_t)NB*KST];      // compressed A
__device__ uint32_t  g_M2[(size_t)256*24*64];  // metadata: [R][c][g*8+s*2+h]
__device__ __half    g_B[(size_t)NO*KSP];      // dense B, silu folded

static __device__ __forceinline__ uint32_t smem_u32(const void* p){
    uint32_t a;
    asm("{ .reg .u64 t; cvta.to.shared.u64 t, %1; cvt.u32.u64 %0, t; }" : "=r"(a) : "l"(p));
    return a;
}
#define SWZ(b) ((b) ^ (((b)>>3)&0x70))

__constant__ int cPA[6] = {0,5,1,2,3,7};
__constant__ int cPB[6] = {4,9,8,6,10,64};

// ---- features + metadata: thread = (b, ip) ----
__global__ void __launch_bounds__(256) feat_kernel(const float* __restrict__ X){
    int gtid = blockIdx.x*256 + threadIdx.x;
    int b = gtid>>7, ip = gtid&127;
    float2 xv = *(const float2*)(X + (size_t)b*NI + ip*2);
    uint32_t P0[2], P1[2]; int T[2];
    float xa[2] = {xv.x, xv.y};
    #pragma unroll
    for (int l=0; l<2; ++l){
        float xs = 8.0f*xa[l];
        int t = (int)floorf(xs); t = min(max(t,0),7);
        float u = xs - (float)t, v = 1.0f-u;
        float u2=u*u, u3=u2*u, v3=v*v*v;
        float w0 = v3*(1.0f/6.0f);
        float w1 = (3.0f*u3-6.0f*u2+4.0f)*(1.0f/6.0f);
        float w2 = (-3.0f*u3+3.0f*u2+3.0f*u+1.0f)*(1.0f/6.0f);
        float w3 = u3*(1.0f/6.0f);
        __half2 h01=__floats2half2_rn(w0,w1), h23=__floats2half2_rn(w2,w3);
        P0[l]=*(uint32_t*)&h01; P1[l]=*(uint32_t*)&h23; T[l]=t;
    }
    const int R = b>>4, g = b&7, hb = (b>>3)&1;
    uint16_t* M16 = (uint16_t*)g_M2;
    #pragma unroll
    for (int p=0; p<6; ++p){
        uint32_t nib = 8u; __half v[2];
        #pragma unroll
        for (int l=0; l<2; ++l){
            int da = cPA[p]-T[l], db = cPB[p]-T[l];
            bool aA = (unsigned)da<=3u, aB = (unsigned)db<=3u;
            int d = aA ? da : db;
            uint32_t c = (d<2) ? P0[l] : P1[l];
            __half2 hc = *(__half2*)&c;
            __half val = (d&1) ? __high2half(hc) : __low2half(hc);
            if (!(aA||aB)) val = __ushort_as_half((unsigned short)0);
            v[l] = val;
            uint32_t e = (!aA && aB) ? 1u : 0u;
            nib |= l ? (e<<2) : e;
        }
        *(__half2*)(g_A + (size_t)b*KST + p*256 + ip*2) = __halves2half2(v[0],v[1]);
        // metadata half-word: 4 nibbles across ip group of 4
        uint32_t w = nib << ((ip&3)*4);
        w |= __shfl_xor_sync(~0u, w, 1);
        w |= __shfl_xor_sync(~0u, w, 2);
        if ((ip&3)==0){
            int c  = p*4 + (ip>>5);
            int il = ip&31;
            int s  = il>>3, h = (il>>2)&1;
            size_t idx = ((((size_t)R*24 + c)*64 + g*8 + s*2 + h) << 1) | (size_t)hb;
            M16[idx] = (uint16_t)w;
        }
    }
}

// ---- weights: B[o, p*512 + ip*4 + l*2 + {0,1}] = sf*(cp+gamma) ----
__global__ void __launch_bounds__(256) prep_kernel(const float* __restrict__ CP,
                                                   const float* __restrict__ SF){
    __shared__ float sv[13], gam[11];
    int o = blockIdx.x, i = threadIdx.x;
    if (i<13){ float c = -0.25f + 0.125f*i; sv[i] = c/(1.0f+expf(-c)); }
    __syncthreads();
    if (i<11) gam[i] = (8.0f*sv[i+1]-sv[i]-sv[i+2])*(1.0f/6.0f);
    __syncthreads();
    int ip = i>>1, l = i&1;
    float sfv = SF[(size_t)i*NO + o];
    const float* cp = CP + ((size_t)i*NO + o)*19;
    #pragma unroll
    for (int p=0; p<6; ++p){
        float wa = sfv*(cp[8+cPA[p]] + gam[cPA[p]]);
        float wb = (p==5) ? 0.0f : sfv*(cp[8+cPB[p]] + gam[cPB[p]]);
        *(__half2*)(g_B + (size_t)o*KSP + p*512 + ip*4 + l*2) = __floats2half2_rn(wa,wb);
    }
}

// ---- sparse GEMM: M=64 x N=128, 8 warps, mma.sp.m16n8k32 ----
// smem: A 3x8K @0 | B 3x32K @24576 | meta 3x1K @122880 -> 125952 B
__global__ void __launch_bounds__(256) gemm_kernel(float* __restrict__ out){
    extern __shared__ uint8_t smem[];
    const uint32_t sb = smem_u32(smem);
    const int tid = threadIdx.x, wid = tid>>5, lane = tid&31;
    const int mbase = blockIdx.x*64, nbase = blockIdx.y*128;
    const int mrow0 = (wid>>2)*32, ncol0 = (wid&3)*32;
    const int lrow = lane&7, sub = lane>>3;
    const int a_row = mrow0 + (sub&1)*8 + lrow;
    const int a_q   = sub>>1;
    const int b_rowo = (sub>>1)*8 + lrow;
    const int b_q   = sub&1;
    const int Rbase = mbase>>4;

    float acc[2][4][4] = {};

    auto issue_copy = [&](int c, int s){
        #pragma unroll
        for (int it=0; it<11; ++it){
            int idx = tid + it*256;
            if (idx < 512){
                int r = idx>>3, q = idx&7;
                const __half* src = g_A + (size_t)(mbase+r)*KST + c*64 + q*8;
                uint32_t dst = sb + (uint32_t)s*8192u + SWZ((uint32_t)(r*128+q*16));
                asm volatile("cp.async.cg.shared.global [%0], [%1], 16;"
                             :: "r"(dst), "l"(__cvta_generic_to_global(src)));
            } else if (idx < 2560){
                int j = idx-512, n = j>>4, h = (j>>3)&1, q = j&7;
                const __half* src = g_B + (size_t)(nbase+n)*KSP + c*128 + h*64 + q*8;
                uint32_t dst = sb + 24576u + (uint32_t)s*32768u + (uint32_t)h*16384u
                             + SWZ((uint32_t)(n*128+q*16));
                asm volatile("cp.async.cg.shared.global [%0], [%1], 16;"
                             :: "r"(dst), "l"(__cvta_generic_to_global(src)));
            } else if (idx < 2624){
                int r = idx-2560;           // 0..63: R'=r>>4, 16B group w4=r&15
                int Rp = r>>4, w4 = r&15;
                const uint32_t* src = g_M2 + ((size_t)(Rbase+Rp)*24 + c)*64 + w4*4;
                uint32_t dst = sb + 122880u + (uint32_t)s*1024u + (uint32_t)(Rp*256 + w4*16);
                asm volatile("cp.async.cg.shared.global [%0], [%1], 16;"
                             :: "r"(dst), "l"(__cvta_generic_to_global(src)));
            }
        }
    };

    issue_copy(0,0);
    asm volatile("cp.async.commit_group;" ::: "memory");
    issue_copy(1,1);
    asm volatile("cp.async.commit_group;" ::: "memory");

    int s_cur=0, s_nxt=2;
    #pragma unroll 1
    for (int c=0; c<NCH; ++c){
        if (c < NCH-2){ asm volatile("cp.async.wait_group 1;" ::: "memory"); }
        else          { asm volatile("cp.async.wait_group 0;" ::: "memory"); }
        __syncthreads();
        if (c+2 < NCH){
            issue_copy(c+2, s_nxt);
            asm volatile("cp.async.commit_group;" ::: "memory");
        }
        const uint32_t Ab = sb + (uint32_t)s_cur*8192u;
        const uint32_t Bb = sb + 24576u + (uint32_t)s_cur*32768u;
        const uint32_t Mb = sb + 122880u + (uint32_t)s_cur*1024u;
        #pragma unroll
        for (int s=0; s<4; ++s){
            uint32_t a[2][4];
            #pragma unroll
            for (int mt=0; mt<2; ++mt){
                uint32_t addr = Ab + SWZ((uint32_t)((a_row+mt*16)*128 + (s*2+a_q)*16));
                asm volatile("ldmatrix.sync.aligned.m8n8.x4.shared.b16 {%0,%1,%2,%3}, [%4];"
                    : "=r"(a[mt][0]),"=r"(a[mt][1]),"=r"(a[mt][2]),"=r"(a[mt][3]) : "r"(addr));
            }
            uint32_t bf[2][2][4];
            #pragma unroll
            for (int h=0; h<2; ++h){
                int subt = s>>1, kq = (s&1)*2 + h;
                #pragma unroll
                for (int np=0; np<2; ++np){
                    uint32_t addr = Bb + (uint32_t)subt*16384u
                        + SWZ((uint32_t)((ncol0+np*16+b_rowo)*128 + (kq*2+b_q)*16));
                    asm volatile("ldmatrix.sync.aligned.m8n8.x4.shared.b16 {%0,%1,%2,%3}, [%4];"
                        : "=r"(bf[h][np][0]),"=r"(bf[h][np][1]),
                          "=r"(bf[h][np][2]),"=r"(bf[h][np][3]) : "r"(addr));
                }
            }
            // metadata, layout B: T0/T1 of quad hold rows (g, g+8), k-half = lane&1
            uint32_t meta[2];
            #pragma unroll
            for (int mt=0; mt<2; ++mt){
                uint32_t maddr = Mb + (uint32_t)((((wid>>2)*2 + mt)*256)
                               + (lane>>2)*32 + s*8 + (lane&1)*4);
                asm volatile("ld.shared.b32 %0, [%1];" : "=r"(meta[mt]) : "r"(maddr));
            }
            #pragma unroll
            for (int mt=0; mt<2; ++mt)
                #pragma unroll
                for (int nt=0; nt<4; ++nt){
                    int np = nt>>1, hh = (nt&1)*2;
                    asm volatile(
                        "mma.sp.sync.aligned.m16n8k32.row.col.f32.f16.f16.f32 "
                        "{%0,%1,%2,%3}, {%4,%5,%6,%7}, {%8,%9,%10,%11}, {%0,%1,%2,%3}, %12, 0x0;"
                        : "+f"(acc[mt][nt][0]),"+f"(acc[mt][nt][1]),
                          "+f"(acc[mt][nt][2]),"+f"(acc[mt][nt][3])
                        : "r"(a[mt][0]),"r"(a[mt][1]),"r"(a[mt][2]),"r"(a[mt][3]),
                          "r"(bf[0][np][hh]),"r"(bf[0][np][hh+1]),
                          "r"(bf[1][np][hh]),"r"(bf[1][np][hh+1]),
                          "r"(meta[mt]));
                }
        }
        s_cur = (s_cur==2)?0:s_cur+1;
        s_nxt = (s_nxt==2)?0:s_nxt+1;
    }

    const int g = lane>>2, tt = lane&3;
    #pragma unroll
    for (int mt=0; mt<2; ++mt)
        #pragma unroll
        for (int nt=0; nt<4; ++nt){
            int row = mbase + mrow0 + mt*16 + g;
            int col = nbase + ncol0 + nt*8 + tt*2;
            *(float2*)(out + (size_t)row*NO + col)
                = make_float2(acc[mt][nt][0], acc[mt][nt][1]);
            *(float2*)(out + (size_t)(row+8)*NO + col)
                = make_float2(acc[mt][nt][2], acc[mt][nt][3]);
        }
}

extern "C" void kernel_launch(void* const* d_in, const int* in_sizes, int n_in,
                              void* d_out, int out_size){
    const float *x=nullptr, *cp=nullptr, *sf=nullptr;
    for (int i=0; i<n_in; ++i){
        if      (in_sizes[i] == NB*NI)    x  = (const float*)d_in[i];
        else if (in_sizes[i] == NI*NO*19) cp = (const float*)d_in[i];
        else if (in_sizes[i] == NI*NO)    sf = (const float*)d_in[i];
    }
    static bool once = false;
    if (!once){
        cudaFuncSetAttribute(gemm_kernel, cudaFuncAttributeMaxDynamicSharedMemorySize, 125952);
        once = true;
    }
    feat_kernel<<<(NB*NI/2)/256, 256>>>(x);
    prep_kernel<<<NO, 256>>>(cp, sf);
    gemm_kernel<<<dim3(NB/64, NO/128), 256, 125952>>>((float*)d_out);
}

// round 16
// speedup vs baseline: 2.4110x; 2.4110x over previous
#include <cuda_runtime.h>
#include <cuda_fp16.h>
#include <cstdint>
#include <math.h>

// R15: warp-specialized fused GEMM. Warps 0-3 = MMA consumers, warps 4-7 =
// producers (A features from X + B cp.async). K = 2816 (silu folded via
// quasi-interpolation). B layout: k = (q*11 + j)*64 + il, i = q*64 + il.
// Tile M=64 x N=64, grid 256 CTAs, smem 40KB -> 2 CTAs/SM.

#define NB 4096
#define NI 256
#define NO 256
#define KT 2816
#define NCH 44

__device__ __half g_B[(size_t)NO*KT];   // folded weights, 1.4 MB

static __device__ __forceinline__ uint32_t smem_u32(const void* p){
    uint32_t a;
    asm("{ .reg .u64 t; cvta.to.shared.u64 t, %1; cvt.u32.u64 %0, t; }" : "=r"(a) : "l"(p));
    return a;
}
#define SWZ(b) ((b) ^ (((b)>>3)&0x70))

// ---- weights: B[o, (i>>6)*704 + j*64 + (i&63)] = sf*(cp[8+j]+gamma_j) ----
__global__ void __launch_bounds__(256) prep_kernel(const float* __restrict__ CP,
                                                   const float* __restrict__ SF){
    __shared__ float sv[13], gam[11];
    int o = blockIdx.x, i = threadIdx.x;
    if (i<13){ float c = -0.25f + 0.125f*i; sv[i] = c/(1.0f+expf(-c)); }
    __syncthreads();
    if (i<11) gam[i] = (8.0f*sv[i+1]-sv[i]-sv[i+2])*(1.0f/6.0f);
    __syncthreads();
    float sfv = SF[(size_t)i*NO + o];
    const float* cp = CP + ((size_t)i*NO + o)*19;
    __half* dst = g_B + (size_t)o*KT + (i>>6)*704 + (i&63);
    #pragma unroll
    for (int j=0; j<11; ++j)
        dst[j*64] = __float2half_rn(sfv*(cp[8+j] + gam[j]));
}

// ---- fused warp-specialized GEMM ----
// smem: A 2x8KB @0 | B 3x8KB @16384. Total 40960.
__global__ void __launch_bounds__(256,2) gemm_kernel(const float* __restrict__ X,
                                                     float* __restrict__ out){
    extern __shared__ uint8_t smem[];
    const uint32_t sb = smem_u32(smem);
    const int tid = threadIdx.x;
    const int mbase = blockIdx.x*64;
    const int nbase = blockIdx.y*64;

    if (tid < 128){
        // ================= CONSUMERS (warps 0-3) =================
        const int wid = tid>>5, lane = tid&31;
        const int mrow0 = (wid>>1)*32, ncol0 = (wid&1)*32;
        const int lrow = lane&7, sub = lane>>3;
        const int a_row = mrow0 + (sub&1)*8 + lrow;
        const int a_q   = sub>>1;
        const int b_rowo = (sub>>1)*8 + lrow;
        const int b_q   = sub&1;
        float acc[2][4][4] = {};

        #pragma unroll 1
        for (int c=0; c<NCH; ++c){
            __syncthreads();   // A_c, B_c visible
            const uint32_t Ab = sb + (uint32_t)(c&1)*8192u;
            const uint32_t Bb = sb + 16384u + (uint32_t)(c%3)*8192u;
            #pragma unroll
            for (int ks=0; ks<4; ++ks){
                uint32_t a[2][4];
                #pragma unroll
                for (int mt=0; mt<2; ++mt){
                    uint32_t addr = Ab + SWZ((uint32_t)((a_row+mt*16)*128 + (ks*2+a_q)*16));
                    asm volatile("ldmatrix.sync.aligned.m8n8.x4.shared.b16 {%0,%1,%2,%3}, [%4];"
                        : "=r"(a[mt][0]),"=r"(a[mt][1]),"=r"(a[mt][2]),"=r"(a[mt][3]) : "r"(addr));
                }
                uint32_t b[2][4];
                #pragma unroll
                for (int np=0; np<2; ++np){
                    uint32_t addr = Bb + SWZ((uint32_t)((ncol0+np*16+b_rowo)*128 + (ks*2+b_q)*16));
                    asm volatile("ldmatrix.sync.aligned.m8n8.x4.shared.b16 {%0,%1,%2,%3}, [%4];"
                        : "=r"(b[np][0]),"=r"(b[np][1]),"=r"(b[np][2]),"=r"(b[np][3]) : "r"(addr));
                }
                #pragma unroll
                for (int mt=0; mt<2; ++mt)
                    #pragma unroll
                    for (int nt=0; nt<4; ++nt){
                        uint32_t b0 = b[nt>>1][(nt&1)*2], b1 = b[nt>>1][(nt&1)*2+1];
                        asm volatile(
                            "mma.sync.aligned.m16n8k16.row.col.f32.f16.f16.f32 "
                            "{%0,%1,%2,%3}, {%4,%5,%6,%7}, {%8,%9}, {%0,%1,%2,%3};"
                            : "+f"(acc[mt][nt][0]),"+f"(acc[mt][nt][1]),
                              "+f"(acc[mt][nt][2]),"+f"(acc[mt][nt][3])
                            : "r"(a[mt][0]),"r"(a[mt][1]),"r"(a[mt][2]),"r"(a[mt][3]),
                              "r"(b0),"r"(b1));
                    }
            }
        }
        // epilogue
        const int g = lane>>2, tt = lane&3;
        #pragma unroll
        for (int mt=0; mt<2; ++mt)
            #pragma unroll
            for (int nt=0; nt<4; ++nt){
                int row = mbase + mrow0 + mt*16 + g;
                int col = nbase + ncol0 + nt*8 + tt*2;
                *(float2*)(out + (size_t)row*NO + col)
                    = make_float2(acc[mt][nt][0], acc[mt][nt][1]);
                *(float2*)(out + (size_t)(row+8)*NO + col)
                    = make_float2(acc[mt][nt][2], acc[mt][nt][3]);
            }
    } else {
        // ================= PRODUCERS (warps 4-7) =================
        const int ptid = tid - 128;
        const int rA = ptid & 63;        // A row
        const int seg = ptid >> 6;       // i-segment (32 i's) within 64-i block
        uint32_t W01[32], W23[32], Tpk[4];

        auto issueB = [&](int c, int s){
            const int kb = c*64;
            #pragma unroll
            for (int it=0; it<4; ++it){
                int idx = ptid + it*128;
                int r = idx>>3, q = idx&7;
                const __half* src = g_B + (size_t)(nbase+r)*KT + kb + q*8;
                uint32_t dst = sb + 16384u + (uint32_t)s*8192u + SWZ((uint32_t)(r*128+q*16));
                asm volatile("cp.async.cg.shared.global [%0], [%1], 16;"
                             :: "r"(dst), "l"(__cvta_generic_to_global(src)));
            }
        };
        auto precompute = [&](int q){
            const float* xr = X + (size_t)(mbase+rA)*NI + q*64 + seg*32;
            Tpk[0]=Tpk[1]=Tpk[2]=Tpk[3]=0;
            #pragma unroll
            for (int q4=0; q4<8; ++q4){
                float4 xv = *(const float4*)(xr + q4*4);
                float xa[4] = {xv.x, xv.y, xv.z, xv.w};
                #pragma unroll
                for (int m=0; m<4; ++m){
                    int e = q4*4 + m;
                    float xs = 8.0f*xa[m];
                    float tf = floorf(xs);
                    int ti = (int)tf;
                    float u = xs - tf, v = 1.0f-u;
                    float u2=u*u, u3=u2*u, v3=v*v*v;
                    float w0 = v3*(1.0f/6.0f);
                    float w1 = (3.0f*u3-6.0f*u2+4.0f)*(1.0f/6.0f);
                    float w2 = (-3.0f*u3+3.0f*u2+3.0f*u+1.0f)*(1.0f/6.0f);
                    float w3 = u3*(1.0f/6.0f);
                    __half2 h01=__floats2half2_rn(w0,w1), h23=__floats2half2_rn(w2,w3);
                    W01[e]=*(uint32_t*)&h01; W23[e]=*(uint32_t*)&h23;
                    Tpk[e>>3] |= (uint32_t)ti << ((e&7)*4);
                }
            }
        };
        auto computeA = [&](int j, int buf){
            uint32_t outp[16];
            #pragma unroll
            for (int p=0; p<16; ++p){
                int e0 = 2*p, e1 = e0+1;
                int t0 = (Tpk[e0>>3] >> ((e0&7)*4)) & 7;
                int t1 = (Tpk[e1>>3] >> ((e1&7)*4)) & 7;
                int d0 = j - t0, d1 = j - t1;
                uint32_t ca = (d0<2) ? W01[e0] : W23[e0];
                uint32_t cb = (d1<2) ? W01[e1] : W23[e1];
                __half2 ha = *(__half2*)&ca, hb = *(__half2*)&cb;
                __half v0 = (d0&1) ? __high2half(ha) : __low2half(ha);
                __half v1 = (d1&1) ? __high2half(hb) : __low2half(hb);
                if ((unsigned)d0 > 3u) v0 = __ushort_as_half((unsigned short)0);
                if ((unsigned)d1 > 3u) v1 = __ushort_as_half((unsigned short)0);
                __half2 hv = __halves2half2(v0, v1);
                outp[p] = *(uint32_t*)&hv;
            }
            uint8_t* base = smem + (uint32_t)buf*8192u;
            uint32_t o0 = (uint32_t)(rA*128 + seg*64);
            #pragma unroll
            for (int w=0; w<4; ++w)
                *(uint4*)(base + SWZ(o0 + w*16))
                    = make_uint4(outp[w*4],outp[w*4+1],outp[w*4+2],outp[w*4+3]);
        };

        issueB(0,0);
        asm volatile("cp.async.commit_group;" ::: "memory");
        issueB(1,1);
        asm volatile("cp.async.commit_group;" ::: "memory");
        precompute(0);
        computeA(0, 0);
        asm volatile("cp.async.wait_group 1;" ::: "memory");   // B_0 done

        int jj = 0, qq = 0;
        #pragma unroll 1
        for (int c=0; c<NCH; ++c){
            __syncthreads();   // publish A_c, B_c; consumers done with old buffers
            if (c+2 < NCH){
                issueB(c+2, (c+2)%3);
                asm volatile("cp.async.commit_group;" ::: "memory");
            }
            if (c+1 < NCH){
                if (jj == 10){ precompute(qq+1); computeA(0, (c+1)&1); }
                else         { computeA(jj+1, (c+1)&1); }
            }
            if (c < NCH-2){ asm volatile("cp.async.wait_group 1;" ::: "memory"); }
            else          { asm volatile("cp.async.wait_group 0;" ::: "memory"); }
            if (++jj == 11){ jj = 0; ++qq; }
        }
    }
}

extern "C" void kernel_launch(void* const* d_in, const int* in_sizes, int n_in,
                              void* d_out, int out_size){
    const float *x=nullptr, *cp=nullptr, *sf=nullptr;
    for (int i=0; i<n_in; ++i){
        if      (in_sizes[i] == NB*NI)    x  = (const float*)d_in[i];
        else if (in_sizes[i] == NI*NO*19) cp = (const float*)d_in[i];
        else if (in_sizes[i] == NI*NO)    sf = (const float*)d_in[i];
    }
    prep_kernel<<<NO, 256>>>(cp, sf);
    gemm_kernel<<<dim3(NB/64, NO/64), 256, 40960>>>(x, (float*)d_out);
}

// round 17
// speedup vs baseline: 3.5998x; 1.4931x over previous
#include <cuda_runtime.h>
#include <cuda_fp16.h>
#include <cstdint>
#include <math.h>

// R16 = R11 with a deeper gemm pipeline: 6 stages (96 KB smem, occ 2),
// one barrier per 2 chunks (22 syncs), prefetch depth 4, wait_group 2.
// feat / prep / MMA core byte-identical to R11 (passed, rel 2.2e-4).
// Layout: k = ip*22 + 2j + l, K = 2816 (silu folded via quasi-interpolation).

#define NB 4096
#define NI 256
#define NO 256
#define KS 2816
#define NCH 44

__device__ __half g_A[(size_t)NB*KS];   // spline features, 23 MB
__device__ __half g_B[(size_t)NO*KS];   // folded weights, 1.4 MB

static __device__ __forceinline__ uint32_t smem_u32(const void* p){
    uint32_t a;
    asm("{ .reg .u64 t; cvta.to.shared.u64 t, %1; cvt.u32.u64 %0, t; }" : "=r"(a) : "l"(p));
    return a;
}
#define SWZ(b) ((b) ^ (((b)>>3)&0x70))

// ---- kernel 1: spline features, one thread per element pair ----
__global__ void __launch_bounds__(256) feat_kernel(const float* __restrict__ X){
    __shared__ __align__(16) uint8_t sl[2*5632];
    const int tid = threadIdx.x;
    const int gtid = blockIdx.x*256 + tid;
    const int b = gtid>>7, ip = gtid&127;
    float2 xv = *(const float2*)(X + (size_t)b*NI + ip*2);
    uint8_t* slot = sl + (tid>>7)*5632 + ip*44;

    #pragma unroll
    for (int w=0; w<11; ++w) *(uint32_t*)(slot + w*4) = 0u;

    float xa[2] = {xv.x, xv.y};
    #pragma unroll
    for (int l=0; l<2; ++l){
        float x  = xa[l];
        float xs = 8.0f*x;
        float tf = floorf(xs);
        int t = (int)tf;
        t = min(max(t,0),7);
        float u = xs - (float)t;
        float v = 1.0f - u;
        float u2=u*u, u3=u2*u, v3=v*v*v;
        float w0 = v3*(1.0f/6.0f);
        float w1 = (3.0f*u3 - 6.0f*u2 + 4.0f)*(1.0f/6.0f);
        float w2 = (-3.0f*u3 + 3.0f*u2 + 3.0f*u + 1.0f)*(1.0f/6.0f);
        float w3 = u3*(1.0f/6.0f);
        __half h0=__float2half_rn(w0), h1=__float2half_rn(w1);
        __half h2=__float2half_rn(w2), h3=__float2half_rn(w3);
        uint8_t* e = slot + t*4 + l*2;
        *(uint16_t*)(e)      = *(uint16_t*)&h0;
        *(uint16_t*)(e + 4)  = *(uint16_t*)&h1;
        *(uint16_t*)(e + 8)  = *(uint16_t*)&h2;
        *(uint16_t*)(e + 12) = *(uint16_t*)&h3;
    }
    __syncthreads();
    const uint4* s4 = (const uint4*)sl;
    uint4* d4 = (uint4*)(g_A + (size_t)(blockIdx.x*2)*KS);
    for (int k=tid; k<704; k+=256) d4[k] = s4[k];
}

// ---- kernel 2: weights B[o, ip*22+2j+l] = sf*(cp[8+j] + gamma_j) ----
__global__ void __launch_bounds__(256) prep_kernel(const float* __restrict__ CP,
                                                   const float* __restrict__ SF){
    __shared__ __align__(16) uint8_t sl[5632];
    __shared__ float sv[13];
    __shared__ float gam[11];
    int o = blockIdx.x, i = threadIdx.x;
    if (i < 13){
        float c = -0.25f + 0.125f*i;
        sv[i] = c / (1.0f + expf(-c));
    }
    __syncthreads();
    if (i < 11) gam[i] = (8.0f*sv[i+1] - sv[i] - sv[i+2]) * (1.0f/6.0f);
    __syncthreads();
    int ip = i>>1, l = i&1;
    float sfv = SF[(size_t)i*NO + o];
    const float* cp = CP + ((size_t)i*NO + o)*19;
    uint8_t* e = sl + ip*44 + l*2;
    #pragma unroll
    for (int j=0; j<11; ++j){
        __half h = __float2half_rn(sfv*(cp[8+j] + gam[j]));
        *(uint16_t*)(e + j*4) = *(uint16_t*)&h;
    }
    __syncthreads();
    const uint4* s4 = (const uint4*)sl;
    uint4* d4 = (uint4*)(g_B + (size_t)o*KS);
    for (int k=i; k<352; k+=256) d4[k] = s4[k];
}

// ---- kernel 3: GEMM, M=64 x N=64, 8 warps, 6-stage pipeline ----
// smem: A stages 6x8KB @ 0; B stages 6x8KB @ 49152. Total 96 KB, occ 2.
__global__ void __launch_bounds__(256,2) gemm_kernel(float* __restrict__ out){
    extern __shared__ uint8_t smem[];
    const uint32_t sb = smem_u32(smem);
    const int tid = threadIdx.x;
    const int wid = tid>>5, lane = tid&31;
    const int mbase = blockIdx.x*64;
    const int nbase = blockIdx.y*64;
    const int mrow0 = (wid>>2)*32;
    const int ncol0 = (wid&3)*16;

    const int lrow = lane&7, sub = lane>>3;
    const int a_row = mrow0 + (sub&1)*8 + lrow;
    const int a_q   = sub>>1;
    const int b_rowo = (sub>>1)*8 + lrow;
    const int b_q   = sub&1;

    float acc[2][2][4] = {};

    auto issue_copy = [&](int c, int s){
        const int kb = c*64;
        #pragma unroll
        for (int it=0; it<4; ++it){
            int idx = tid + it*256;
            const __half* src;
            uint32_t dst;
            if (idx < 512){
                int r = idx>>3, q = idx&7;
                src = g_A + (size_t)(mbase+r)*KS + kb + q*8;
                dst = sb + (uint32_t)s*8192u + SWZ((uint32_t)(r*128 + q*16));
            } else {
                int jj = idx-512; int r = jj>>3, q = jj&7;
                src = g_B + (size_t)(nbase+r)*KS + kb + q*8;
                dst = sb + 49152u + (uint32_t)s*8192u + SWZ((uint32_t)(r*128 + q*16));
            }
            asm volatile("cp.async.cg.shared.global [%0], [%1], 16;"
                         :: "r"(dst), "l"(__cvta_generic_to_global(src)));
        }
    };

    auto mma_chunk = [&](int s_cur){
        const uint32_t Ab = sb + (uint32_t)s_cur*8192u;
        const uint32_t Bb = sb + 49152u + (uint32_t)s_cur*8192u;
        #pragma unroll
        for (int ks=0; ks<4; ++ks){
            uint32_t a[2][4];
            #pragma unroll
            for (int mt=0; mt<2; ++mt){
                uint32_t addr = Ab + SWZ((uint32_t)((a_row + mt*16)*128 + (ks*2 + a_q)*16));
                asm volatile("ldmatrix.sync.aligned.m8n8.x4.shared.b16 {%0,%1,%2,%3}, [%4];"
                    : "=r"(a[mt][0]),"=r"(a[mt][1]),"=r"(a[mt][2]),"=r"(a[mt][3]) : "r"(addr));
            }
            uint32_t b[4];
            {
                uint32_t addr = Bb + SWZ((uint32_t)((ncol0 + b_rowo)*128 + (ks*2 + b_q)*16));
                asm volatile("ldmatrix.sync.aligned.m8n8.x4.shared.b16 {%0,%1,%2,%3}, [%4];"
                    : "=r"(b[0]),"=r"(b[1]),"=r"(b[2]),"=r"(b[3]) : "r"(addr));
            }
            #pragma unroll
            for (int mt=0; mt<2; ++mt)
                #pragma unroll
                for (int nt=0; nt<2; ++nt){
                    uint32_t b0 = b[nt*2], b1 = b[nt*2+1];
                    asm volatile(
                        "mma.sync.aligned.m16n8k16.row.col.f32.f16.f16.f32 "
                        "{%0,%1,%2,%3}, {%4,%5,%6,%7}, {%8,%9}, {%0,%1,%2,%3};"
                        : "+f"(acc[mt][nt][0]),"+f"(acc[mt][nt][1]),
                          "+f"(acc[mt][nt][2]),"+f"(acc[mt][nt][3])
                        : "r"(a[mt][0]),"r"(a[mt][1]),"r"(a[mt][2]),"r"(a[mt][3]),
                          "r"(b0),"r"(b1));
                }
        }
    };

    // prefetch chunks 0..3
    #pragma unroll
    for (int c=0; c<4; ++c){
        issue_copy(c, c);
        asm volatile("cp.async.commit_group;" ::: "memory");
    }

    #pragma unroll 1
    for (int p=0; p<22; ++p){
        const int c0 = 2*p;
        if (p < 21){ asm volatile("cp.async.wait_group 2;" ::: "memory"); }
        else       { asm volatile("cp.async.wait_group 0;" ::: "memory"); }
        __syncthreads();   // chunks c0, c0+1 resident; stages (c0+4)%6,(c0+5)%6 free
        if (c0+4 < NCH){
            issue_copy(c0+4, (c0+4)%6);
            asm volatile("cp.async.commit_group;" ::: "memory");
        }
        if (c0+5 < NCH){
            issue_copy(c0+5, (c0+5)%6);
            asm volatile("cp.async.commit_group;" ::: "memory");
        }
        mma_chunk(c0 % 6);
        mma_chunk((c0+1) % 6);
    }

    // epilogue: direct fp32 store
    const int g = lane>>2, tt = lane&3;
    #pragma unroll
    for (int mt=0; mt<2; ++mt){
        #pragma unroll
        for (int nt=0; nt<2; ++nt){
            int row = mbase + mrow0 + mt*16 + g;
            int col = nbase + ncol0 + nt*8 + tt*2;
            float2 v0 = make_float2(acc[mt][nt][0], acc[mt][nt][1]);
            float2 v1 = make_float2(acc[mt][nt][2], acc[mt][nt][3]);
            *(float2*)(out + (size_t)row*NO + col)     = v0;
            *(float2*)(out + (size_t)(row+8)*NO + col) = v1;
        }
    }
}

extern "C" void kernel_launch(void* const* d_in, const int* in_sizes, int n_in,
                              void* d_out, int out_size){
    const float *x=nullptr, *cp=nullptr, *sf=nullptr;
    for (int i=0; i<n_in; ++i){
        if      (in_sizes[i] == NB*NI)    x  = (const float*)d_in[i];
        else if (in_sizes[i] == NI*NO*19) cp = (const float*)d_in[i];
        else if (in_sizes[i] == NI*NO)    sf = (const float*)d_in[i];
    }
    static bool attr_done = false;
    if (!attr_done){
        cudaFuncSetAttribute(gemm_kernel, cudaFuncAttributeMaxDynamicSharedMemorySize, 98304);
        attr_done = true;
    }
    feat_kernel<<<(NB/2), 256>>>(x);
    prep_kernel<<<NO, 256>>>(cp, sf);
    gemm_kernel<<<dim3(NB/64, NO/64), 256, 98304>>>((float*)d_out);
}